// round 13
// baseline (speedup 1.0000x reference)
#include <cuda_runtime.h>
#include <cuda_bf16.h>
#include <math.h>
#include <stdint.h>

#define NN    32768
#define KK    1024
#define DHH   512
#define KC2   1024        // stored [hi|lo]; logical K=1536 via chunk remap in loader
#define EPSF  1e-5f
#define NITER 150
#define FBIG  3.402823466e38f
#define NKELT ((size_t)NN * KK)

// GEMM: tile 128(M) x 256(N), 256 threads, mma.sync bf16
#define MT 128
#define NT 256
#define MM_KCH   32
#define MM_NCH   48                  // logical chunks: 3*DHH/32
#define MM_ROWB  80                  // 64B data + 16B pad (bank shift 20 -> conflict-free)
#define MM_STAGE ((MT + NT) * MM_ROWB)   // 30720
#define SMEM_TOT (3 * MM_STAGE)          // 92160

// ---- static device scratch ----
__device__ __align__(16) float g_d[NN * KK];
__device__ __align__(16) __nv_bfloat16 g_zc[(size_t)NN * KC2];   // 64 MB
__device__ __align__(16) __nv_bfloat16 g_mc[(size_t)KK * KC2];   // 2 MB
__device__ float g_a[NN];
__device__ float g_b[KK];
__device__ float g_relz[NN * 5];
__device__ float g_rhoz[NN], g_sigz[NN];
__device__ float g_cspart[64 * KK];
__device__ float g_icolsum[KK];

// ---- helpers ----
__device__ __forceinline__ uint32_t s2u(const void* p) {
    uint32_t a;
    asm("{ .reg .u64 t; cvta.to.shared.u64 t, %1; cvt.u32.u64 %0, t; }"
        : "=r"(a) : "l"(p));
    return a;
}
__device__ __forceinline__ void cpa16(uint32_t dst, const void* src) {
    asm volatile("cp.async.cg.shared.global [%0], [%1], 16;" :: "r"(dst), "l"(src));
}
__device__ __forceinline__ void mma16816(float* c, const uint32_t* a, const uint32_t* b) {
    asm volatile("mma.sync.aligned.m16n8k16.row.col.f32.bf16.bf16.f32 "
        "{%0,%1,%2,%3}, {%4,%5,%6,%7}, {%8,%9}, {%0,%1,%2,%3};"
        : "+f"(c[0]), "+f"(c[1]), "+f"(c[2]), "+f"(c[3])
        : "r"(a[0]), "r"(a[1]), "r"(a[2]), "r"(a[3]), "r"(b[0]), "r"(b[1]));
}

// ---- sorted smallest-5 insertion ----
#define INS5(v, a0, a1, a2, a3, a4) do {                          \
    float _v = (v);                                               \
    if (_v < a4) {                                                \
        a4 = _v;                                                  \
        if (a4 < a3) { float _t = a3; a3 = a4; a4 = _t; }         \
        if (a3 < a2) { float _t = a2; a2 = a3; a3 = _t; }         \
        if (a2 < a1) { float _t = a1; a1 = a2; a2 = _t; }         \
        if (a1 < a0) { float _t = a0; a0 = a1; a1 = _t; }         \
    }                                                             \
} while (0)

// ======================= K0: row stats =======================
__global__ void k_stats(const float* __restrict__ P, float* __restrict__ out,
                        float c2, float cadd) {
    int row  = blockIdx.x * 8 + (threadIdx.x >> 5);
    int lane = threadIdx.x & 31;
    const float* p = P + (size_t)row * DHH;
    float s = 0.f, ss = 0.f;
#pragma unroll
    for (int q = 0; q < 4; ++q) {
        float4 v = *(const float4*)&p[q * 128 + lane * 4];
        s  += (v.x + v.y) + (v.z + v.w);
        ss += v.x * v.x + v.y * v.y + v.z * v.z + v.w * v.w;
    }
#pragma unroll
    for (int off = 16; off > 0; off >>= 1) {
        s  += __shfl_xor_sync(0xffffffffu, s, off);
        ss += __shfl_xor_sync(0xffffffffu, ss, off);
    }
    if (lane == 0) out[row] = ss + c2 * s + cadd;
}

// ======================= K0b: fp32 -> bf16 [hi | lo] =======================
__global__ void k_cvt(const float* __restrict__ X, __nv_bfloat16* __restrict__ C) {
    size_t idx = (size_t)blockIdx.x * 256 + threadIdx.x;
    size_t row = idx >> 7;
    int    c4  = ((int)idx & 127) << 2;
    float4 v = *(const float4*)&X[row * DHH + c4];
    float f[4] = {v.x, v.y, v.z, v.w};
    unsigned short hu[4], lu[4];
#pragma unroll
    for (int i = 0; i < 4; ++i) {
        __nv_bfloat16 h = __float2bfloat16(f[i]);
        __nv_bfloat16 l = __float2bfloat16(f[i] - __bfloat162float(h));
        hu[i] = __bfloat16_as_ushort(h);
        lu[i] = __bfloat16_as_ushort(l);
    }
    uint2 hv = make_uint2(((uint32_t)hu[1] << 16) | hu[0],
                          ((uint32_t)hu[3] << 16) | hu[2]);
    uint2 lv = make_uint2(((uint32_t)lu[1] << 16) | lu[0],
                          ((uint32_t)lu[3] << 16) | lu[2]);
    __nv_bfloat16* base = C + row * KC2 + c4;
    *(uint2*)(base)       = hv;
    *(uint2*)(base + 512) = lv;
}

// ======================= K1: mma.sync GEMM + distance =======================
// logical K=1536 as 48 chunks; chunk c maps to physical panels:
//   Z : c<16 -> hi(c)      16<=c<32 -> lo(c-16)   c>=32 -> hi(c-32)
//   MU: c<16 -> hi(c)      16<=c<32 -> hi(c-16)   c>=32 -> lo(c-32)
__global__ void __launch_bounds__(256, 1) k_gemm() {
    extern __shared__ char smem_raw[];
    const int tid = threadIdx.x;
    const int wid = tid >> 5, lid = tid & 31;
    const int j0 = blockIdx.x * NT;
    const int i0 = blockIdx.y * MT;
    const int g = lid >> 2, t = lid & 3;
    const int wm = wid >> 2, wn = wid & 3;      // warp tile 64(M) x 64(N)
    char* sm = smem_raw;
    uint32_t smu = s2u(sm);

    auto load_chunk = [&](int c) {
        uint32_t st = smu + (uint32_t)(c % 3) * MM_STAGE;
        int zo = (c < 16) ? c * 32 : (c < 32 ? 512 + (c - 16) * 32 : (c - 32) * 32);
        int mo = (c < 16) ? c * 32 : (c < 32 ? (c - 16) * 32 : 512 + (c - 32) * 32);
#pragma unroll
        for (int it = 0; it < 6; ++it) {            // 1536 x 16B per stage
            int idx = tid + it * 256;
            int row = idx >> 2, q = idx & 3;
            const __nv_bfloat16* src = (row < MT)
                ? g_zc + (size_t)(i0 + row) * KC2 + zo + q * 8
                : g_mc + (size_t)(j0 + row - MT) * KC2 + mo + q * 8;
            cpa16(st + (uint32_t)row * MM_ROWB + q * 16, src);
        }
    };

    float cacc[4][8][4];
#pragma unroll
    for (int mi = 0; mi < 4; ++mi)
#pragma unroll
        for (int ni = 0; ni < 8; ++ni)
#pragma unroll
            for (int q = 0; q < 4; ++q) cacc[mi][ni][q] = 0.f;

    load_chunk(0); asm volatile("cp.async.commit_group;" ::: "memory");
    load_chunk(1); asm volatile("cp.async.commit_group;" ::: "memory");
    load_chunk(2); asm volatile("cp.async.commit_group;" ::: "memory");

#pragma unroll 1
    for (int kt = 0; kt < MM_NCH; ++kt) {
        asm volatile("cp.async.wait_group 2;" ::: "memory");
        __syncthreads();
        const char* st = sm + (kt % 3) * MM_STAGE;
        const char* Ab = st + (wm * 64 + g) * MM_ROWB + t * 4;
        const char* Bb = st + MT * MM_ROWB + (wn * 64 + g) * MM_ROWB + t * 4;
#pragma unroll
        for (int ks = 0; ks < 2; ++ks) {
            uint32_t a[4][4], b[8][2];
#pragma unroll
            for (int mi = 0; mi < 4; ++mi) {
                const char* p = Ab + mi * 16 * MM_ROWB + ks * 32;
                a[mi][0] = *(const uint32_t*)(p);
                a[mi][1] = *(const uint32_t*)(p + 8 * MM_ROWB);
                a[mi][2] = *(const uint32_t*)(p + 16);
                a[mi][3] = *(const uint32_t*)(p + 8 * MM_ROWB + 16);
            }
#pragma unroll
            for (int ni = 0; ni < 8; ++ni) {
                const char* p = Bb + ni * 8 * MM_ROWB + ks * 32;
                b[ni][0] = *(const uint32_t*)(p);
                b[ni][1] = *(const uint32_t*)(p + 16);
            }
#pragma unroll
            for (int mi = 0; mi < 4; ++mi)
#pragma unroll
                for (int ni = 0; ni < 8; ++ni)
                    mma16816(cacc[mi][ni], a[mi], b[ni]);
        }
        __syncthreads();
        if (kt + 3 < MM_NCH) load_chunk(kt + 3);
        asm volatile("cp.async.commit_group;" ::: "memory");
    }

    // distance epilogue
#pragma unroll
    for (int mi = 0; mi < 4; ++mi) {
        int r0 = i0 + wm * 64 + mi * 16 + g;
        float a0 = g_a[r0], a1 = g_a[r0 + 8];
#pragma unroll
        for (int ni = 0; ni < 8; ++ni) {
            int cn = j0 + wn * 64 + ni * 8 + t * 2;
            float2 bb = *(const float2*)&g_b[cn];
            float2 o0, o1;
            o0.x = sqrtf(fmaxf(fmaf(-2.f, cacc[mi][ni][0], a0 + bb.x), 0.f));
            o0.y = sqrtf(fmaxf(fmaf(-2.f, cacc[mi][ni][1], a0 + bb.y), 0.f));
            o1.x = sqrtf(fmaxf(fmaf(-2.f, cacc[mi][ni][2], a1 + bb.x), 0.f));
            o1.y = sqrtf(fmaxf(fmaf(-2.f, cacc[mi][ni][3], a1 + bb.y), 0.f));
            *(float2*)&g_d[(size_t)r0 * KK + cn]       = o0;
            *(float2*)&g_d[(size_t)(r0 + 8) * KK + cn] = o1;
        }
    }
}

// ======================= K2: row top-5 =======================
__global__ void k_rowtop5() {
    int row  = blockIdx.x * 8 + (threadIdx.x >> 5);
    int lane = threadIdx.x & 31;
    const float* dr = g_d + (size_t)row * KK;
    float t0 = FBIG, t1 = FBIG, t2 = FBIG, t3 = FBIG, t4 = FBIG;
#pragma unroll 1
    for (int q = 0; q < 8; ++q) {
        float4 v = *(const float4*)&dr[q * 128 + lane * 4];
        float m = fminf(fminf(v.x, v.y), fminf(v.z, v.w));
        if (m < t4) {
            INS5(v.x, t0, t1, t2, t3, t4);
            INS5(v.y, t0, t1, t2, t3, t4);
            INS5(v.z, t0, t1, t2, t3, t4);
            INS5(v.w, t0, t1, t2, t3, t4);
        }
    }
#pragma unroll
    for (int off = 16; off > 0; off >>= 1) {
        float s0 = __shfl_xor_sync(0xffffffffu, t0, off);
        float s1 = __shfl_xor_sync(0xffffffffu, t1, off);
        float s2 = __shfl_xor_sync(0xffffffffu, t2, off);
        float s3 = __shfl_xor_sync(0xffffffffu, t3, off);
        float s4 = __shfl_xor_sync(0xffffffffu, t4, off);
        if (s0 < t4) {
            INS5(s0, t0, t1, t2, t3, t4);
            INS5(s1, t0, t1, t2, t3, t4);
            INS5(s2, t0, t1, t2, t3, t4);
            INS5(s3, t0, t1, t2, t3, t4);
            INS5(s4, t0, t1, t2, t3, t4);
        }
    }
    if (lane == 0) {
        float* o = g_relz + (size_t)row * 5;
        o[0] = t0; o[1] = t1; o[2] = t2; o[3] = t3; o[4] = t4;
    }
}

// ======================= K3: sigma bisection =======================
__global__ void k_solve() {
    int r = blockIdx.x * 256 + threadIdx.x;
    const float* rl = g_relz + (size_t)r * 5;
    float rho = rl[0];
    float e1 = rl[1] - rho, e2 = rl[2] - rho, e3 = rl[3] - rho, e4 = rl[4] - rho;
    float m0 = 0.f, m1 = 10000.f, sg = 1.f;
#pragma unroll 1
    for (int it = 0; it < NITER; ++it) {
        float inv = 1.0f / sg;
        float cur = 1.0f
            + ((e1 > 0.f) ? expf(-e1 * inv) : 1.0f)
            + ((e2 > 0.f) ? expf(-e2 * inv) : 1.0f)
            + ((e3 > 0.f) ? expf(-e3 * inv) : 1.0f)
            + ((e4 > 0.f) ? expf(-e4 * inv) : 1.0f);
        if (cur > 1.5f) m1 = sg; else m0 = sg;
        sg = 0.5f * (m0 + m1);
    }
    g_rhoz[r] = rho;
    g_sigz[r] = sg;
}

// ======================= K4: W1 / S + rowsum =======================
__global__ void k_w1s(float* __restrict__ W1a, float* __restrict__ S,
                      float* __restrict__ W1b) {
    int row  = blockIdx.x * 8 + (threadIdx.x >> 5);
    int lane = threadIdx.x & 31;
    float rho = g_rhoz[row];
    float invs = 1.0f / g_sigz[row];
    const float* dr = g_d + (size_t)row * KK;
    float w[32];
    float s = 0.f;
#pragma unroll
    for (int q = 0; q < 8; ++q) {
        float4 v = *(const float4*)&dr[q * 128 + lane * 4];
        float w0 = (v.x - rho > 0.f) ? expf(-(v.x - rho) * invs) : 1.0f;
        float w1 = (v.y - rho > 0.f) ? expf(-(v.y - rho) * invs) : 1.0f;
        float w2 = (v.z - rho > 0.f) ? expf(-(v.z - rho) * invs) : 1.0f;
        float w3 = (v.w - rho > 0.f) ? expf(-(v.w - rho) * invs) : 1.0f;
        w[q * 4 + 0] = w0; w[q * 4 + 1] = w1; w[q * 4 + 2] = w2; w[q * 4 + 3] = w3;
        s += (w0 + w1) + (w2 + w3);
    }
#pragma unroll
    for (int off = 16; off > 0; off >>= 1)
        s += __shfl_xor_sync(0xffffffffu, s, off);
    float rinv = 1.0f / s;
    size_t base = (size_t)row * KK;
#pragma unroll
    for (int q = 0; q < 8; ++q) {
        size_t o = base + q * 128 + lane * 4;
        float4 wv = make_float4(w[q * 4], w[q * 4 + 1], w[q * 4 + 2], w[q * 4 + 3]);
        float4 sv = make_float4(wv.x * rinv, wv.y * rinv, wv.z * rinv, wv.w * rinv);
        *(float4*)&W1a[o] = wv;
        *(float4*)&W1b[o] = wv;
        *(float4*)&S[o]   = sv;
    }
}

// ======================= K5: colsum(S) =======================
__global__ void k_cspart(const float* __restrict__ S) {
    int col = blockIdx.x * 128 + threadIdx.x;
    const float* p = S + (size_t)blockIdx.y * (NN / 64) * KK + col;
    float acc = 0.f;
#pragma unroll 4
    for (int r = 0; r < NN / 64; ++r) acc += p[(size_t)r * KK];
    g_cspart[blockIdx.y * KK + col] = acc;
}

__global__ void k_csmerge() {
    int col = threadIdx.x;
    float acc = 0.f;
#pragma unroll
    for (int c = 0; c < 64; ++c) acc += g_cspart[c * KK + col];
    g_icolsum[col] = 1.0f / acc;
}

// ======================= K6: D =======================
__global__ void k_D(const float* __restrict__ S, float* __restrict__ D) {
    int row  = blockIdx.x * 8 + (threadIdx.x >> 5);
    int lane = threadIdx.x & 31;
    const float* sr = S + (size_t)row * KK;
    float t[32];
    float acc = 0.f;
#pragma unroll
    for (int q = 0; q < 8; ++q) {
        float4 v  = *(const float4*)&sr[q * 128 + lane * 4];
        float4 ic = *(const float4*)&g_icolsum[q * 128 + lane * 4];
        float t0 = v.x * v.x * ic.x;
        float t1 = v.y * v.y * ic.y;
        float t2 = v.z * v.z * ic.z;
        float t3 = v.w * v.w * ic.w;
        t[q * 4 + 0] = t0; t[q * 4 + 1] = t1; t[q * 4 + 2] = t2; t[q * 4 + 3] = t3;
        acc += (t0 + t1) + (t2 + t3);
    }
#pragma unroll
    for (int off = 16; off > 0; off >>= 1)
        acc += __shfl_xor_sync(0xffffffffu, acc, off);
    float rinv = 1.0f / acc;
    size_t base = (size_t)row * KK;
#pragma unroll
    for (int q = 0; q < 8; ++q) {
        size_t o = base + q * 128 + lane * 4;
        *(float4*)&D[o] = make_float4(t[q * 4] * rinv, t[q * 4 + 1] * rinv,
                                      t[q * 4 + 2] * rinv, t[q * 4 + 3] * rinv);
    }
}

// ======================= launch =======================
extern "C" void kernel_launch(void* const* d_in, const int* in_sizes, int n_in,
                              void* d_out, int out_size) {
    const float* Z  = (const float*)d_in[0];
    const float* MU = (const float*)d_in[1];
    float* out = (float*)d_out;
    float* W1a = out;
    float* S   = out + NKELT;
    float* W1b = out + 2 * NKELT;
    float* D   = out + 3 * NKELT;

    float *pa, *pb;
    __nv_bfloat16 *pzc, *pmc;
    cudaGetSymbolAddress((void**)&pa, g_a);
    cudaGetSymbolAddress((void**)&pb, g_b);
    cudaGetSymbolAddress((void**)&pzc, g_zc);
    cudaGetSymbolAddress((void**)&pmc, g_mc);

    cudaFuncSetAttribute(k_gemm, cudaFuncAttributeMaxDynamicSharedMemorySize,
                         SMEM_TOT);

    k_stats<<<NN / 8, 256>>>(Z, pa,  2.0f * EPSF, 512.0f * EPSF * EPSF);
    k_stats<<<KK / 8, 256>>>(MU, pb, -2.0f * EPSF, 0.0f);
    k_cvt<<<(NN * 128) / 256, 256>>>(Z, pzc);
    k_cvt<<<(KK * 128) / 256, 256>>>(MU, pmc);
    k_gemm<<<dim3(KK / NT, NN / MT), 256, SMEM_TOT>>>();
    k_rowtop5<<<NN / 8, 256>>>();
    k_solve<<<NN / 256, 256>>>();
    k_w1s<<<NN / 8, 256>>>(W1a, S, W1b);
    k_cspart<<<dim3(KK / 128, 64), 128>>>(S);
    k_csmerge<<<1, KK>>>();
    k_D<<<NN / 8, 256>>>(S, D);
}

// round 14
// speedup vs baseline: 1.5071x; 1.5071x over previous
#include <cuda_runtime.h>
#include <cuda_bf16.h>
#include <math.h>
#include <stdint.h>

#define NN    32768
#define KK    1024
#define DHH   512
#define KC2   1024        // stored [hi|lo]; logical K=1536 via chunk remap in loader
#define EPSF  1e-5f
#define NITER 150
#define FBIG  3.402823466e38f
#define NKELT ((size_t)NN * KK)

// GEMM: tile 128(M) x 256(N), 256 threads, mma.sync bf16
#define MT 128
#define NT 256
#define MM_KCH   32
#define MM_NCH   48                  // logical chunks: 3*DHH/32
#define MM_ROWB  80                  // 64B data + 16B pad (bank shift 20 -> conflict-free)
#define MM_STAGE ((MT + NT) * MM_ROWB)   // 30720
#define SM5_OFF  (3 * MM_STAGE)          // 92160
#define SMEM_TOT (SM5_OFF + 128 * 4 * 5 * 4)  // 102400

// ---- static device scratch ----
__device__ __align__(16) float g_d[NN * KK];
__device__ __align__(16) __nv_bfloat16 g_zc[(size_t)NN * KC2];   // 64 MB
__device__ __align__(16) __nv_bfloat16 g_mc[(size_t)KK * KC2];   // 2 MB
__device__ float g_a[NN];
__device__ float g_b[KK];
__device__ float g_t5p[NN * 4 * 5];                 // per-panel row top-5 partials
__device__ float g_rhoz[NN], g_sigz[NN];
__device__ float g_cspart[(size_t)(NN / 8) * KK];   // colsum(S) partials (16 MB)
__device__ float g_cs2[32 * KK];                    // second-level partials
__device__ float g_icolsum[KK];

// ---- helpers ----
__device__ __forceinline__ uint32_t s2u(const void* p) {
    uint32_t a;
    asm("{ .reg .u64 t; cvta.to.shared.u64 t, %1; cvt.u32.u64 %0, t; }"
        : "=r"(a) : "l"(p));
    return a;
}
__device__ __forceinline__ void cpa16(uint32_t dst, const void* src) {
    asm volatile("cp.async.cg.shared.global [%0], [%1], 16;" :: "r"(dst), "l"(src));
}
__device__ __forceinline__ void mma16816(float* c, const uint32_t* a, const uint32_t* b) {
    asm volatile("mma.sync.aligned.m16n8k16.row.col.f32.bf16.bf16.f32 "
        "{%0,%1,%2,%3}, {%4,%5,%6,%7}, {%8,%9}, {%0,%1,%2,%3};"
        : "+f"(c[0]), "+f"(c[1]), "+f"(c[2]), "+f"(c[3])
        : "r"(a[0]), "r"(a[1]), "r"(a[2]), "r"(a[3]), "r"(b[0]), "r"(b[1]));
}

// ---- sorted smallest-5 insertion ----
#define INS5(v, a0, a1, a2, a3, a4) do {                          \
    float _v = (v);                                               \
    if (_v < a4) {                                                \
        a4 = _v;                                                  \
        if (a4 < a3) { float _t = a3; a3 = a4; a4 = _t; }         \
        if (a3 < a2) { float _t = a2; a2 = a3; a3 = _t; }         \
        if (a2 < a1) { float _t = a1; a1 = a2; a2 = _t; }         \
        if (a1 < a0) { float _t = a0; a0 = a1; a1 = _t; }         \
    }                                                             \
} while (0)

// ======================= K0: row stats =======================
__global__ void k_stats(const float* __restrict__ P, float* __restrict__ out,
                        float c2, float cadd) {
    int row  = blockIdx.x * 8 + (threadIdx.x >> 5);
    int lane = threadIdx.x & 31;
    const float* p = P + (size_t)row * DHH;
    float s = 0.f, ss = 0.f;
#pragma unroll
    for (int q = 0; q < 4; ++q) {
        float4 v = *(const float4*)&p[q * 128 + lane * 4];
        s  += (v.x + v.y) + (v.z + v.w);
        ss += v.x * v.x + v.y * v.y + v.z * v.z + v.w * v.w;
    }
#pragma unroll
    for (int off = 16; off > 0; off >>= 1) {
        s  += __shfl_xor_sync(0xffffffffu, s, off);
        ss += __shfl_xor_sync(0xffffffffu, ss, off);
    }
    if (lane == 0) out[row] = ss + c2 * s + cadd;
}

// ======================= K0b: fp32 -> bf16 [hi | lo] =======================
__global__ void k_cvt(const float* __restrict__ X, __nv_bfloat16* __restrict__ C) {
    size_t idx = (size_t)blockIdx.x * 256 + threadIdx.x;
    size_t row = idx >> 7;
    int    c4  = ((int)idx & 127) << 2;
    float4 v = *(const float4*)&X[row * DHH + c4];
    float f[4] = {v.x, v.y, v.z, v.w};
    unsigned short hu[4], lu[4];
#pragma unroll
    for (int i = 0; i < 4; ++i) {
        __nv_bfloat16 h = __float2bfloat16(f[i]);
        __nv_bfloat16 l = __float2bfloat16(f[i] - __bfloat162float(h));
        hu[i] = __bfloat16_as_ushort(h);
        lu[i] = __bfloat16_as_ushort(l);
    }
    uint2 hv = make_uint2(((uint32_t)hu[1] << 16) | hu[0],
                          ((uint32_t)hu[3] << 16) | hu[2]);
    uint2 lv = make_uint2(((uint32_t)lu[1] << 16) | lu[0],
                          ((uint32_t)lu[3] << 16) | lu[2]);
    __nv_bfloat16* base = C + row * KC2 + c4;
    *(uint2*)(base)       = hv;
    *(uint2*)(base + 512) = lv;
}

// ======================= K1: mma.sync GEMM + distance + row-top5 partials ===========
// logical K=1536 as 48 chunks; chunk c maps to physical panels:
//   Z : c<16 -> hi(c)      16<=c<32 -> lo(c-16)   c>=32 -> hi(c-32)
//   MU: c<16 -> hi(c)      16<=c<32 -> hi(c-16)   c>=32 -> lo(c-32)
__global__ void __launch_bounds__(256, 1) k_gemm() {
    extern __shared__ char smem_raw[];
    const int tid = threadIdx.x;
    const int wid = tid >> 5, lid = tid & 31;
    const int j0 = blockIdx.x * NT;
    const int i0 = blockIdx.y * MT;
    const int g = lid >> 2, t = lid & 3;
    const int wm = wid >> 2, wn = wid & 3;      // warp tile 64(M) x 64(N)
    char* sm = smem_raw;
    uint32_t smu = s2u(sm);
    float* sm5 = (float*)(smem_raw + SM5_OFF);   // [128 rows][4 wn][5]

    auto load_chunk = [&](int c) {
        uint32_t st = smu + (uint32_t)(c % 3) * MM_STAGE;
        int zo = (c < 16) ? c * 32 : (c < 32 ? 512 + (c - 16) * 32 : (c - 32) * 32);
        int mo = (c < 16) ? c * 32 : (c < 32 ? (c - 16) * 32 : 512 + (c - 32) * 32);
#pragma unroll
        for (int it = 0; it < 6; ++it) {            // 1536 x 16B per stage
            int idx = tid + it * 256;
            int row = idx >> 2, q = idx & 3;
            const __nv_bfloat16* src = (row < MT)
                ? g_zc + (size_t)(i0 + row) * KC2 + zo + q * 8
                : g_mc + (size_t)(j0 + row - MT) * KC2 + mo + q * 8;
            cpa16(st + (uint32_t)row * MM_ROWB + q * 16, src);
        }
    };

    float cacc[4][8][4];
#pragma unroll
    for (int mi = 0; mi < 4; ++mi)
#pragma unroll
        for (int ni = 0; ni < 8; ++ni)
#pragma unroll
            for (int q = 0; q < 4; ++q) cacc[mi][ni][q] = 0.f;

    load_chunk(0); asm volatile("cp.async.commit_group;" ::: "memory");
    load_chunk(1); asm volatile("cp.async.commit_group;" ::: "memory");
    load_chunk(2); asm volatile("cp.async.commit_group;" ::: "memory");

#pragma unroll 1
    for (int kt = 0; kt < MM_NCH; ++kt) {
        asm volatile("cp.async.wait_group 2;" ::: "memory");
        __syncthreads();
        const char* st = sm + (kt % 3) * MM_STAGE;
        const char* Ab = st + (wm * 64 + g) * MM_ROWB + t * 4;
        const char* Bb = st + MT * MM_ROWB + (wn * 64 + g) * MM_ROWB + t * 4;
#pragma unroll
        for (int ks = 0; ks < 2; ++ks) {
            uint32_t a[4][4], b[8][2];
#pragma unroll
            for (int mi = 0; mi < 4; ++mi) {
                const char* p = Ab + mi * 16 * MM_ROWB + ks * 32;
                a[mi][0] = *(const uint32_t*)(p);
                a[mi][1] = *(const uint32_t*)(p + 8 * MM_ROWB);
                a[mi][2] = *(const uint32_t*)(p + 16);
                a[mi][3] = *(const uint32_t*)(p + 8 * MM_ROWB + 16);
            }
#pragma unroll
            for (int ni = 0; ni < 8; ++ni) {
                const char* p = Bb + ni * 8 * MM_ROWB + ks * 32;
                b[ni][0] = *(const uint32_t*)(p);
                b[ni][1] = *(const uint32_t*)(p + 16);
            }
#pragma unroll
            for (int mi = 0; mi < 4; ++mi)
#pragma unroll
                for (int ni = 0; ni < 8; ++ni)
                    mma16816(cacc[mi][ni], a[mi], b[ni]);
        }
        __syncthreads();
        if (kt + 3 < MM_NCH) load_chunk(kt + 3);
        asm volatile("cp.async.commit_group;" ::: "memory");
    }

    // ---- epilogue: distance + per-warp row-top5 ----
#pragma unroll
    for (int mi = 0; mi < 4; ++mi) {
        int r0 = i0 + wm * 64 + mi * 16 + g;
        float a0 = g_a[r0], a1 = g_a[r0 + 8];
        float p0 = FBIG, p1 = FBIG, p2 = FBIG, p3 = FBIG, p4 = FBIG;  // row r0
        float q0 = FBIG, q1 = FBIG, q2 = FBIG, q3 = FBIG, q4 = FBIG;  // row r0+8
#pragma unroll
        for (int ni = 0; ni < 8; ++ni) {
            int cn = j0 + wn * 64 + ni * 8 + t * 2;
            float2 bb = *(const float2*)&g_b[cn];
            float2 o0, o1;
            o0.x = sqrtf(fmaxf(fmaf(-2.f, cacc[mi][ni][0], a0 + bb.x), 0.f));
            o0.y = sqrtf(fmaxf(fmaf(-2.f, cacc[mi][ni][1], a0 + bb.y), 0.f));
            o1.x = sqrtf(fmaxf(fmaf(-2.f, cacc[mi][ni][2], a1 + bb.x), 0.f));
            o1.y = sqrtf(fmaxf(fmaf(-2.f, cacc[mi][ni][3], a1 + bb.y), 0.f));
            *(float2*)&g_d[(size_t)r0 * KK + cn]       = o0;
            *(float2*)&g_d[(size_t)(r0 + 8) * KK + cn] = o1;
            INS5(o0.x, p0, p1, p2, p3, p4);
            INS5(o0.y, p0, p1, p2, p3, p4);
            INS5(o1.x, q0, q1, q2, q3, q4);
            INS5(o1.y, q0, q1, q2, q3, q4);
        }
        // merge across the 4 t-lanes of each quad (butterfly)
#pragma unroll
        for (int off = 1; off <= 2; off <<= 1) {
            float s0 = __shfl_xor_sync(0xffffffffu, p0, off);
            float s1 = __shfl_xor_sync(0xffffffffu, p1, off);
            float s2 = __shfl_xor_sync(0xffffffffu, p2, off);
            float s3 = __shfl_xor_sync(0xffffffffu, p3, off);
            float s4 = __shfl_xor_sync(0xffffffffu, p4, off);
            INS5(s0, p0, p1, p2, p3, p4);
            INS5(s1, p0, p1, p2, p3, p4);
            INS5(s2, p0, p1, p2, p3, p4);
            INS5(s3, p0, p1, p2, p3, p4);
            INS5(s4, p0, p1, p2, p3, p4);
            s0 = __shfl_xor_sync(0xffffffffu, q0, off);
            s1 = __shfl_xor_sync(0xffffffffu, q1, off);
            s2 = __shfl_xor_sync(0xffffffffu, q2, off);
            s3 = __shfl_xor_sync(0xffffffffu, q3, off);
            s4 = __shfl_xor_sync(0xffffffffu, q4, off);
            INS5(s0, q0, q1, q2, q3, q4);
            INS5(s1, q0, q1, q2, q3, q4);
            INS5(s2, q0, q1, q2, q3, q4);
            INS5(s3, q0, q1, q2, q3, q4);
            INS5(s4, q0, q1, q2, q3, q4);
        }
        if (t == 0) {
            int rl0 = wm * 64 + mi * 16 + g;
            float* d0 = sm5 + ((size_t)rl0 * 4 + wn) * 5;
            d0[0] = p0; d0[1] = p1; d0[2] = p2; d0[3] = p3; d0[4] = p4;
            float* d1 = sm5 + ((size_t)(rl0 + 8) * 4 + wn) * 5;
            d1[0] = q0; d1[1] = q1; d1[2] = q2; d1[3] = q3; d1[4] = q4;
        }
    }
    __syncthreads();
    // cross-wn merge: one thread per row
    if (tid < 128) {
        float t0 = FBIG, t1 = FBIG, t2 = FBIG, t3 = FBIG, t4 = FBIG;
        const float* p = sm5 + (size_t)tid * 20;
#pragma unroll
        for (int q = 0; q < 20; ++q) INS5(p[q], t0, t1, t2, t3, t4);
        float* o = g_t5p + ((size_t)(i0 + tid) * 4 + blockIdx.x) * 5;
        o[0] = t0; o[1] = t1; o[2] = t2; o[3] = t3; o[4] = t4;
    }
}

// ======================= K3: merge panel top5 + sigma bisection =======================
__global__ void k_solve() {
    int r = blockIdx.x * 256 + threadIdx.x;
    const float* pl = g_t5p + (size_t)r * 20;
    float t0 = FBIG, t1 = FBIG, t2 = FBIG, t3 = FBIG, t4 = FBIG;
#pragma unroll
    for (int q = 0; q < 20; ++q) INS5(pl[q], t0, t1, t2, t3, t4);
    float rho = t0;
    float e1 = t1 - rho, e2 = t2 - rho, e3 = t3 - rho, e4 = t4 - rho;
    float m0 = 0.f, m1 = 10000.f, sg = 1.f;
#pragma unroll 1
    for (int it = 0; it < NITER; ++it) {
        float inv = 1.0f / sg;
        float cur = 1.0f
            + ((e1 > 0.f) ? expf(-e1 * inv) : 1.0f)
            + ((e2 > 0.f) ? expf(-e2 * inv) : 1.0f)
            + ((e3 > 0.f) ? expf(-e3 * inv) : 1.0f)
            + ((e4 > 0.f) ? expf(-e4 * inv) : 1.0f);
        if (cur > 1.5f) m1 = sg; else m0 = sg;
        sg = 0.5f * (m0 + m1);
    }
    g_rhoz[r] = rho;
    g_sigz[r] = sg;
}

// ======================= K4: W1 / S + rowsum + colsum partial =======================
__global__ void __launch_bounds__(256) k_w1s(float* __restrict__ W1a,
                                             float* __restrict__ S,
                                             float* __restrict__ W1b) {
    __shared__ float sc[8][KK];
    int wid  = threadIdx.x >> 5;
    int lane = threadIdx.x & 31;
    int row  = blockIdx.x * 8 + wid;
    float rho = g_rhoz[row];
    float invs = 1.0f / g_sigz[row];
    const float* dr = g_d + (size_t)row * KK;
    float w[32];
    float s = 0.f;
#pragma unroll
    for (int q = 0; q < 8; ++q) {
        float4 v = *(const float4*)&dr[q * 128 + lane * 4];
        float w0 = (v.x - rho > 0.f) ? expf(-(v.x - rho) * invs) : 1.0f;
        float w1 = (v.y - rho > 0.f) ? expf(-(v.y - rho) * invs) : 1.0f;
        float w2 = (v.z - rho > 0.f) ? expf(-(v.z - rho) * invs) : 1.0f;
        float w3 = (v.w - rho > 0.f) ? expf(-(v.w - rho) * invs) : 1.0f;
        w[q * 4 + 0] = w0; w[q * 4 + 1] = w1; w[q * 4 + 2] = w2; w[q * 4 + 3] = w3;
        s += (w0 + w1) + (w2 + w3);
    }
#pragma unroll
    for (int off = 16; off > 0; off >>= 1)
        s += __shfl_xor_sync(0xffffffffu, s, off);
    float rinv = 1.0f / s;
    size_t base = (size_t)row * KK;
#pragma unroll
    for (int q = 0; q < 8; ++q) {
        size_t o = base + q * 128 + lane * 4;
        float4 wv = make_float4(w[q * 4], w[q * 4 + 1], w[q * 4 + 2], w[q * 4 + 3]);
        float4 sv = make_float4(wv.x * rinv, wv.y * rinv, wv.z * rinv, wv.w * rinv);
        *(float4*)&W1a[o] = wv;
        *(float4*)&W1b[o] = wv;
        *(float4*)&S[o]   = sv;
        *(float4*)&sc[wid][q * 128 + lane * 4] = sv;
    }
    __syncthreads();
    int c4 = threadIdx.x * 4;
    float4 acc = make_float4(0.f, 0.f, 0.f, 0.f);
#pragma unroll
    for (int w2 = 0; w2 < 8; ++w2) {
        float4 v = *(const float4*)&sc[w2][c4];
        acc.x += v.x; acc.y += v.y; acc.z += v.z; acc.w += v.w;
    }
    *(float4*)&g_cspart[(size_t)blockIdx.x * KK + c4] = acc;
}

// ======================= K5: two-level colsum merge (coalesced) =======================
__global__ void k_csmerge1() {
    int col = blockIdx.x * 128 + threadIdx.x;
    const float* p = g_cspart + (size_t)blockIdx.y * 128 * KK + col;
    float acc = 0.f;
#pragma unroll 8
    for (int r = 0; r < 128; ++r) acc += p[(size_t)r * KK];
    g_cs2[blockIdx.y * KK + col] = acc;
}

__global__ void k_csmerge2() {
    int col = blockIdx.x * 128 + threadIdx.x;
    float acc = 0.f;
#pragma unroll
    for (int c = 0; c < 32; ++c) acc += g_cs2[c * KK + col];
    g_icolsum[col] = 1.0f / acc;
}

// ======================= K6: D =======================
__global__ void k_D(const float* __restrict__ S, float* __restrict__ D) {
    int row  = blockIdx.x * 8 + (threadIdx.x >> 5);
    int lane = threadIdx.x & 31;
    const float* sr = S + (size_t)row * KK;
    float t[32];
    float acc = 0.f;
#pragma unroll
    for (int q = 0; q < 8; ++q) {
        float4 v  = *(const float4*)&sr[q * 128 + lane * 4];
        float4 ic = *(const float4*)&g_icolsum[q * 128 + lane * 4];
        float t0 = v.x * v.x * ic.x;
        float t1 = v.y * v.y * ic.y;
        float t2 = v.z * v.z * ic.z;
        float t3 = v.w * v.w * ic.w;
        t[q * 4 + 0] = t0; t[q * 4 + 1] = t1; t[q * 4 + 2] = t2; t[q * 4 + 3] = t3;
        acc += (t0 + t1) + (t2 + t3);
    }
#pragma unroll
    for (int off = 16; off > 0; off >>= 1)
        acc += __shfl_xor_sync(0xffffffffu, acc, off);
    float rinv = 1.0f / acc;
    size_t base = (size_t)row * KK;
#pragma unroll
    for (int q = 0; q < 8; ++q) {
        size_t o = base + q * 128 + lane * 4;
        *(float4*)&D[o] = make_float4(t[q * 4] * rinv, t[q * 4 + 1] * rinv,
                                      t[q * 4 + 2] * rinv, t[q * 4 + 3] * rinv);
    }
}

// ======================= launch =======================
extern "C" void kernel_launch(void* const* d_in, const int* in_sizes, int n_in,
                              void* d_out, int out_size) {
    const float* Z  = (const float*)d_in[0];
    const float* MU = (const float*)d_in[1];
    float* out = (float*)d_out;
    float* W1a = out;
    float* S   = out + NKELT;
    float* W1b = out + 2 * NKELT;
    float* D   = out + 3 * NKELT;

    float *pa, *pb;
    __nv_bfloat16 *pzc, *pmc;
    cudaGetSymbolAddress((void**)&pa, g_a);
    cudaGetSymbolAddress((void**)&pb, g_b);
    cudaGetSymbolAddress((void**)&pzc, g_zc);
    cudaGetSymbolAddress((void**)&pmc, g_mc);

    cudaFuncSetAttribute(k_gemm, cudaFuncAttributeMaxDynamicSharedMemorySize,
                         SMEM_TOT);

    k_stats<<<NN / 8, 256>>>(Z, pa,  2.0f * EPSF, 512.0f * EPSF * EPSF);
    k_stats<<<KK / 8, 256>>>(MU, pb, -2.0f * EPSF, 0.0f);
    k_cvt<<<(NN * 128) / 256, 256>>>(Z, pzc);
    k_cvt<<<(KK * 128) / 256, 256>>>(MU, pmc);
    k_gemm<<<dim3(KK / NT, NN / MT), 256, SMEM_TOT>>>();
    k_solve<<<NN / 256, 256>>>();
    k_w1s<<<NN / 8, 256>>>(W1a, S, W1b);
    k_csmerge1<<<dim3(KK / 128, 32), 128>>>();
    k_csmerge2<<<KK / 128, 128>>>();
    k_D<<<NN / 8, 256>>>(S, D);
}

// round 15
// speedup vs baseline: 1.5370x; 1.0198x over previous
#include <cuda_runtime.h>
#include <cuda_bf16.h>
#include <math.h>
#include <stdint.h>

#define NN    32768
#define KK    1024
#define DHH   512
#define KC2   1024        // stored [hi|lo]; logical K=1536 via chunk remap in loader
#define EPSF  1e-5f
#define NITER 150
#define FBIG  3.402823466e38f
#define NKELT ((size_t)NN * KK)

// GEMM: tile 128(M) x 256(N), 256 threads, mma.sync bf16
#define MT 128
#define NT 256
#define MM_KCH   32
#define MM_NCH   48                  // logical chunks: 3*DHH/32
#define MM_ROWB  80                  // 64B data + 16B pad (bank shift 20 -> conflict-free)
#define MM_STAGE ((MT + NT) * MM_ROWB)   // 30720
#define SM5_OFF  (3 * MM_STAGE)          // 92160
#define SMEM_TOT (SM5_OFF + 128 * 4 * 5 * 4)  // 102400

// ---- static device scratch ----
__device__ __align__(16) float g_d[NN * KK];
__device__ __align__(16) __nv_bfloat16 g_zc[(size_t)NN * KC2];   // 64 MB
__device__ __align__(16) __nv_bfloat16 g_mc[(size_t)KK * KC2];   // 2 MB
__device__ float g_a[NN];
__device__ float g_b[KK];
__device__ float g_t5p[NN * 4 * 5];                 // per-panel row top-5 partials
__device__ float g_rhoz[NN], g_sigz[NN];
__device__ float g_cspart[(size_t)(NN / 8) * KK];   // colsum(S) partials (16 MB)
__device__ float g_cs2[32 * KK];                    // second-level partials
__device__ float g_icolsum[KK];

// ---- helpers ----
__device__ __forceinline__ uint32_t s2u(const void* p) {
    uint32_t a;
    asm("{ .reg .u64 t; cvta.to.shared.u64 t, %1; cvt.u32.u64 %0, t; }"
        : "=r"(a) : "l"(p));
    return a;
}
__device__ __forceinline__ void cpa16(uint32_t dst, const void* src) {
    asm volatile("cp.async.cg.shared.global [%0], [%1], 16;" :: "r"(dst), "l"(src));
}
__device__ __forceinline__ void mma16816(float* c, const uint32_t* a, const uint32_t* b) {
    asm volatile("mma.sync.aligned.m16n8k16.row.col.f32.bf16.bf16.f32 "
        "{%0,%1,%2,%3}, {%4,%5,%6,%7}, {%8,%9}, {%0,%1,%2,%3};"
        : "+f"(c[0]), "+f"(c[1]), "+f"(c[2]), "+f"(c[3])
        : "r"(a[0]), "r"(a[1]), "r"(a[2]), "r"(a[3]), "r"(b[0]), "r"(b[1]));
}

// ---- sorted smallest-5 insertion ----
#define INS5(v, a0, a1, a2, a3, a4) do {                          \
    float _v = (v);                                               \
    if (_v < a4) {                                                \
        a4 = _v;                                                  \
        if (a4 < a3) { float _t = a3; a3 = a4; a4 = _t; }         \
        if (a3 < a2) { float _t = a2; a2 = a3; a3 = _t; }         \
        if (a2 < a1) { float _t = a1; a1 = a2; a2 = _t; }         \
        if (a1 < a0) { float _t = a0; a0 = a1; a1 = _t; }         \
    }                                                             \
} while (0)

// ======================= K0: fused row stats + bf16 [hi|lo] conversion ==============
// One warp per row: read the 512-float row once, emit stats AND converted panels.
__global__ void k_statscvt(const float* __restrict__ P, float* __restrict__ outstat,
                           __nv_bfloat16* __restrict__ C, float c2, float cadd) {
    int row  = blockIdx.x * 8 + (threadIdx.x >> 5);
    int lane = threadIdx.x & 31;
    const float* p = P + (size_t)row * DHH;
    __nv_bfloat16* cb = C + (size_t)row * KC2;
    float s = 0.f, ss = 0.f;
#pragma unroll
    for (int q = 0; q < 4; ++q) {
        int col = q * 128 + lane * 4;
        float4 v = *(const float4*)&p[col];
        s  += (v.x + v.y) + (v.z + v.w);
        ss += v.x * v.x + v.y * v.y + v.z * v.z + v.w * v.w;
        float f[4] = {v.x, v.y, v.z, v.w};
        unsigned short hu[4], lu[4];
#pragma unroll
        for (int i = 0; i < 4; ++i) {
            __nv_bfloat16 h = __float2bfloat16(f[i]);
            __nv_bfloat16 l = __float2bfloat16(f[i] - __bfloat162float(h));
            hu[i] = __bfloat16_as_ushort(h);
            lu[i] = __bfloat16_as_ushort(l);
        }
        uint2 hv = make_uint2(((uint32_t)hu[1] << 16) | hu[0],
                              ((uint32_t)hu[3] << 16) | hu[2]);
        uint2 lv = make_uint2(((uint32_t)lu[1] << 16) | lu[0],
                              ((uint32_t)lu[3] << 16) | lu[2]);
        *(uint2*)(cb + col)       = hv;
        *(uint2*)(cb + col + 512) = lv;
    }
#pragma unroll
    for (int off = 16; off > 0; off >>= 1) {
        s  += __shfl_xor_sync(0xffffffffu, s, off);
        ss += __shfl_xor_sync(0xffffffffu, ss, off);
    }
    if (lane == 0) outstat[row] = ss + c2 * s + cadd;
}

// ======================= K1: mma.sync GEMM + distance + row-top5 partials ===========
// logical K=1536 as 48 chunks; chunk c maps to physical panels:
//   Z : c<16 -> hi(c)      16<=c<32 -> lo(c-16)   c>=32 -> hi(c-32)
//   MU: c<16 -> hi(c)      16<=c<32 -> hi(c-16)   c>=32 -> lo(c-32)
__global__ void __launch_bounds__(256, 1) k_gemm() {
    extern __shared__ char smem_raw[];
    const int tid = threadIdx.x;
    const int wid = tid >> 5, lid = tid & 31;
    const int j0 = blockIdx.x * NT;
    const int i0 = blockIdx.y * MT;
    const int g = lid >> 2, t = lid & 3;
    const int wm = wid >> 2, wn = wid & 3;      // warp tile 64(M) x 64(N)
    char* sm = smem_raw;
    uint32_t smu = s2u(sm);
    float* sm5 = (float*)(smem_raw + SM5_OFF);   // [128 rows][4 wn][5]

    auto load_chunk = [&](int c) {
        uint32_t st = smu + (uint32_t)(c % 3) * MM_STAGE;
        int zo = (c < 16) ? c * 32 : (c < 32 ? 512 + (c - 16) * 32 : (c - 32) * 32);
        int mo = (c < 16) ? c * 32 : (c < 32 ? (c - 16) * 32 : 512 + (c - 32) * 32);
#pragma unroll
        for (int it = 0; it < 6; ++it) {            // 1536 x 16B per stage
            int idx = tid + it * 256;
            int row = idx >> 2, q = idx & 3;
            const __nv_bfloat16* src = (row < MT)
                ? g_zc + (size_t)(i0 + row) * KC2 + zo + q * 8
                : g_mc + (size_t)(j0 + row - MT) * KC2 + mo + q * 8;
            cpa16(st + (uint32_t)row * MM_ROWB + q * 16, src);
        }
    };

    float cacc[4][8][4];
#pragma unroll
    for (int mi = 0; mi < 4; ++mi)
#pragma unroll
        for (int ni = 0; ni < 8; ++ni)
#pragma unroll
            for (int q = 0; q < 4; ++q) cacc[mi][ni][q] = 0.f;

    load_chunk(0); asm volatile("cp.async.commit_group;" ::: "memory");
    load_chunk(1); asm volatile("cp.async.commit_group;" ::: "memory");
    load_chunk(2); asm volatile("cp.async.commit_group;" ::: "memory");

#pragma unroll 1
    for (int kt = 0; kt < MM_NCH; ++kt) {
        asm volatile("cp.async.wait_group 2;" ::: "memory");
        __syncthreads();
        const char* st = sm + (kt % 3) * MM_STAGE;
        const char* Ab = st + (wm * 64 + g) * MM_ROWB + t * 4;
        const char* Bb = st + MT * MM_ROWB + (wn * 64 + g) * MM_ROWB + t * 4;
#pragma unroll
        for (int ks = 0; ks < 2; ++ks) {
            uint32_t a[4][4], b[8][2];
#pragma unroll
            for (int mi = 0; mi < 4; ++mi) {
                const char* p = Ab + mi * 16 * MM_ROWB + ks * 32;
                a[mi][0] = *(const uint32_t*)(p);
                a[mi][1] = *(const uint32_t*)(p + 8 * MM_ROWB);
                a[mi][2] = *(const uint32_t*)(p + 16);
                a[mi][3] = *(const uint32_t*)(p + 8 * MM_ROWB + 16);
            }
#pragma unroll
            for (int ni = 0; ni < 8; ++ni) {
                const char* p = Bb + ni * 8 * MM_ROWB + ks * 32;
                b[ni][0] = *(const uint32_t*)(p);
                b[ni][1] = *(const uint32_t*)(p + 16);
            }
#pragma unroll
            for (int mi = 0; mi < 4; ++mi)
#pragma unroll
                for (int ni = 0; ni < 8; ++ni)
                    mma16816(cacc[mi][ni], a[mi], b[ni]);
        }
        __syncthreads();
        if (kt + 3 < MM_NCH) load_chunk(kt + 3);
        asm volatile("cp.async.commit_group;" ::: "memory");
    }

    // ---- epilogue: distance + per-warp row-top5 ----
#pragma unroll
    for (int mi = 0; mi < 4; ++mi) {
        int r0 = i0 + wm * 64 + mi * 16 + g;
        float a0 = g_a[r0], a1 = g_a[r0 + 8];
        float p0 = FBIG, p1 = FBIG, p2 = FBIG, p3 = FBIG, p4 = FBIG;  // row r0
        float q0 = FBIG, q1 = FBIG, q2 = FBIG, q3 = FBIG, q4 = FBIG;  // row r0+8
#pragma unroll
        for (int ni = 0; ni < 8; ++ni) {
            int cn = j0 + wn * 64 + ni * 8 + t * 2;
            float2 bb = *(const float2*)&g_b[cn];
            float2 o0, o1;
            o0.x = sqrtf(fmaxf(fmaf(-2.f, cacc[mi][ni][0], a0 + bb.x), 0.f));
            o0.y = sqrtf(fmaxf(fmaf(-2.f, cacc[mi][ni][1], a0 + bb.y), 0.f));
            o1.x = sqrtf(fmaxf(fmaf(-2.f, cacc[mi][ni][2], a1 + bb.x), 0.f));
            o1.y = sqrtf(fmaxf(fmaf(-2.f, cacc[mi][ni][3], a1 + bb.y), 0.f));
            *(float2*)&g_d[(size_t)r0 * KK + cn]       = o0;
            *(float2*)&g_d[(size_t)(r0 + 8) * KK + cn] = o1;
            INS5(o0.x, p0, p1, p2, p3, p4);
            INS5(o0.y, p0, p1, p2, p3, p4);
            INS5(o1.x, q0, q1, q2, q3, q4);
            INS5(o1.y, q0, q1, q2, q3, q4);
        }
        // merge across the 4 t-lanes of each quad (butterfly)
#pragma unroll
        for (int off = 1; off <= 2; off <<= 1) {
            float s0 = __shfl_xor_sync(0xffffffffu, p0, off);
            float s1 = __shfl_xor_sync(0xffffffffu, p1, off);
            float s2 = __shfl_xor_sync(0xffffffffu, p2, off);
            float s3 = __shfl_xor_sync(0xffffffffu, p3, off);
            float s4 = __shfl_xor_sync(0xffffffffu, p4, off);
            INS5(s0, p0, p1, p2, p3, p4);
            INS5(s1, p0, p1, p2, p3, p4);
            INS5(s2, p0, p1, p2, p3, p4);
            INS5(s3, p0, p1, p2, p3, p4);
            INS5(s4, p0, p1, p2, p3, p4);
            s0 = __shfl_xor_sync(0xffffffffu, q0, off);
            s1 = __shfl_xor_sync(0xffffffffu, q1, off);
            s2 = __shfl_xor_sync(0xffffffffu, q2, off);
            s3 = __shfl_xor_sync(0xffffffffu, q3, off);
            s4 = __shfl_xor_sync(0xffffffffu, q4, off);
            INS5(s0, q0, q1, q2, q3, q4);
            INS5(s1, q0, q1, q2, q3, q4);
            INS5(s2, q0, q1, q2, q3, q4);
            INS5(s3, q0, q1, q2, q3, q4);
            INS5(s4, q0, q1, q2, q3, q4);
        }
        if (t == 0) {
            int rl0 = wm * 64 + mi * 16 + g;
            float* d0 = sm5 + ((size_t)rl0 * 4 + wn) * 5;
            d0[0] = p0; d0[1] = p1; d0[2] = p2; d0[3] = p3; d0[4] = p4;
            float* d1 = sm5 + ((size_t)(rl0 + 8) * 4 + wn) * 5;
            d1[0] = q0; d1[1] = q1; d1[2] = q2; d1[3] = q3; d1[4] = q4;
        }
    }
    __syncthreads();
    // cross-wn merge: one thread per row
    if (tid < 128) {
        float t0 = FBIG, t1 = FBIG, t2 = FBIG, t3 = FBIG, t4 = FBIG;
        const float* p = sm5 + (size_t)tid * 20;
#pragma unroll
        for (int q = 0; q < 20; ++q) INS5(p[q], t0, t1, t2, t3, t4);
        float* o = g_t5p + ((size_t)(i0 + tid) * 4 + blockIdx.x) * 5;
        o[0] = t0; o[1] = t1; o[2] = t2; o[3] = t3; o[4] = t4;
    }
}

// ======================= K3: merge panel top5 + sigma bisection =======================
__global__ void k_solve() {
    int r = blockIdx.x * 256 + threadIdx.x;
    const float* pl = g_t5p + (size_t)r * 20;
    float t0 = FBIG, t1 = FBIG, t2 = FBIG, t3 = FBIG, t4 = FBIG;
#pragma unroll
    for (int q = 0; q < 20; ++q) INS5(pl[q], t0, t1, t2, t3, t4);
    float rho = t0;
    float e1 = t1 - rho, e2 = t2 - rho, e3 = t3 - rho, e4 = t4 - rho;
    float m0 = 0.f, m1 = 10000.f, sg = 1.f;
#pragma unroll 1
    for (int it = 0; it < NITER; ++it) {
        float inv = 1.0f / sg;
        float cur = 1.0f
            + ((e1 > 0.f) ? expf(-e1 * inv) : 1.0f)
            + ((e2 > 0.f) ? expf(-e2 * inv) : 1.0f)
            + ((e3 > 0.f) ? expf(-e3 * inv) : 1.0f)
            + ((e4 > 0.f) ? expf(-e4 * inv) : 1.0f);
        if (cur > 1.5f) m1 = sg; else m0 = sg;
        sg = 0.5f * (m0 + m1);
    }
    g_rhoz[r] = rho;
    g_sigz[r] = sg;
}

// ======================= K4: W1 / S + rowsum + colsum partial =======================
__global__ void __launch_bounds__(256) k_w1s(float* __restrict__ W1a,
                                             float* __restrict__ S,
                                             float* __restrict__ W1b) {
    __shared__ float sc[8][KK];
    int wid  = threadIdx.x >> 5;
    int lane = threadIdx.x & 31;
    int row  = blockIdx.x * 8 + wid;
    float rho = g_rhoz[row];
    float invs = 1.0f / g_sigz[row];
    const float* dr = g_d + (size_t)row * KK;
    float w[32];
    float s = 0.f;
#pragma unroll
    for (int q = 0; q < 8; ++q) {
        float4 v = *(const float4*)&dr[q * 128 + lane * 4];
        float w0 = (v.x - rho > 0.f) ? expf(-(v.x - rho) * invs) : 1.0f;
        float w1 = (v.y - rho > 0.f) ? expf(-(v.y - rho) * invs) : 1.0f;
        float w2 = (v.z - rho > 0.f) ? expf(-(v.z - rho) * invs) : 1.0f;
        float w3 = (v.w - rho > 0.f) ? expf(-(v.w - rho) * invs) : 1.0f;
        w[q * 4 + 0] = w0; w[q * 4 + 1] = w1; w[q * 4 + 2] = w2; w[q * 4 + 3] = w3;
        s += (w0 + w1) + (w2 + w3);
    }
#pragma unroll
    for (int off = 16; off > 0; off >>= 1)
        s += __shfl_xor_sync(0xffffffffu, s, off);
    float rinv = 1.0f / s;
    size_t base = (size_t)row * KK;
#pragma unroll
    for (int q = 0; q < 8; ++q) {
        size_t o = base + q * 128 + lane * 4;
        float4 wv = make_float4(w[q * 4], w[q * 4 + 1], w[q * 4 + 2], w[q * 4 + 3]);
        float4 sv = make_float4(wv.x * rinv, wv.y * rinv, wv.z * rinv, wv.w * rinv);
        *(float4*)&W1a[o] = wv;
        *(float4*)&W1b[o] = wv;
        *(float4*)&S[o]   = sv;
        *(float4*)&sc[wid][q * 128 + lane * 4] = sv;
    }
    __syncthreads();
    int c4 = threadIdx.x * 4;
    float4 acc = make_float4(0.f, 0.f, 0.f, 0.f);
#pragma unroll
    for (int w2 = 0; w2 < 8; ++w2) {
        float4 v = *(const float4*)&sc[w2][c4];
        acc.x += v.x; acc.y += v.y; acc.z += v.z; acc.w += v.w;
    }
    *(float4*)&g_cspart[(size_t)blockIdx.x * KK + c4] = acc;
}

// ======================= K5: two-level colsum merge (coalesced) =======================
__global__ void k_csmerge1() {
    int col = blockIdx.x * 128 + threadIdx.x;
    const float* p = g_cspart + (size_t)blockIdx.y * 128 * KK + col;
    float acc = 0.f;
#pragma unroll 8
    for (int r = 0; r < 128; ++r) acc += p[(size_t)r * KK];
    g_cs2[blockIdx.y * KK + col] = acc;
}

__global__ void k_csmerge2() {
    int col = blockIdx.x * 128 + threadIdx.x;
    float acc = 0.f;
#pragma unroll
    for (int c = 0; c < 32; ++c) acc += g_cs2[c * KK + col];
    g_icolsum[col] = 1.0f / acc;
}

// ======================= K6: D =======================
__global__ void k_D(const float* __restrict__ S, float* __restrict__ D) {
    int row  = blockIdx.x * 8 + (threadIdx.x >> 5);
    int lane = threadIdx.x & 31;
    const float* sr = S + (size_t)row * KK;
    float t[32];
    float acc = 0.f;
#pragma unroll
    for (int q = 0; q < 8; ++q) {
        float4 v  = *(const float4*)&sr[q * 128 + lane * 4];
        float4 ic = *(const float4*)&g_icolsum[q * 128 + lane * 4];
        float t0 = v.x * v.x * ic.x;
        float t1 = v.y * v.y * ic.y;
        float t2 = v.z * v.z * ic.z;
        float t3 = v.w * v.w * ic.w;
        t[q * 4 + 0] = t0; t[q * 4 + 1] = t1; t[q * 4 + 2] = t2; t[q * 4 + 3] = t3;
        acc += (t0 + t1) + (t2 + t3);
    }
#pragma unroll
    for (int off = 16; off > 0; off >>= 1)
        acc += __shfl_xor_sync(0xffffffffu, acc, off);
    float rinv = 1.0f / acc;
    size_t base = (size_t)row * KK;
#pragma unroll
    for (int q = 0; q < 8; ++q) {
        size_t o = base + q * 128 + lane * 4;
        *(float4*)&D[o] = make_float4(t[q * 4] * rinv, t[q * 4 + 1] * rinv,
                                      t[q * 4 + 2] * rinv, t[q * 4 + 3] * rinv);
    }
}

// ======================= launch =======================
extern "C" void kernel_launch(void* const* d_in, const int* in_sizes, int n_in,
                              void* d_out, int out_size) {
    const float* Z  = (const float*)d_in[0];
    const float* MU = (const float*)d_in[1];
    float* out = (float*)d_out;
    float* W1a = out;
    float* S   = out + NKELT;
    float* W1b = out + 2 * NKELT;
    float* D   = out + 3 * NKELT;

    float *pa, *pb;
    __nv_bfloat16 *pzc, *pmc;
    cudaGetSymbolAddress((void**)&pa, g_a);
    cudaGetSymbolAddress((void**)&pb, g_b);
    cudaGetSymbolAddress((void**)&pzc, g_zc);
    cudaGetSymbolAddress((void**)&pmc, g_mc);

    cudaFuncSetAttribute(k_gemm, cudaFuncAttributeMaxDynamicSharedMemorySize,
                         SMEM_TOT);

    k_statscvt<<<NN / 8, 256>>>(Z, pa, pzc,   2.0f * EPSF, 512.0f * EPSF * EPSF);
    k_statscvt<<<KK / 8, 256>>>(MU, pb, pmc, -2.0f * EPSF, 0.0f);
    k_gemm<<<dim3(KK / NT, NN / MT), 256, SMEM_TOT>>>();
    k_solve<<<NN / 256, 256>>>();
    k_w1s<<<NN / 8, 256>>>(W1a, S, W1b);
    k_csmerge1<<<dim3(KK / 128, 32), 128>>>();
    k_csmerge2<<<KK / 128, 128>>>();
    k_D<<<NN / 8, 256>>>(S, D);
}

// round 16
// speedup vs baseline: 1.5926x; 1.0362x over previous
#include <cuda_runtime.h>
#include <cuda_bf16.h>
#include <math.h>
#include <stdint.h>

#define NN    32768
#define KK    1024
#define DHH   512
#define KC2   1024        // stored [hi|lo]; logical K=1536 via chunk remap in loader
#define EPSF  1e-5f
#define NITER 64          // bisection: interval < 1 ulp after 64 halvings (ref does 150; iterations beyond collapse are no-ops)
#define FBIG  3.402823466e38f
#define NKELT ((size_t)NN * KK)

// GEMM: tile 128(M) x 256(N), 256 threads, mma.sync bf16
#define MT 128
#define NT 256
#define MM_KCH   32
#define MM_NCH   48                  // logical chunks: 3*DHH/32
#define MM_ROWB  80                  // 64B data + 16B pad (bank shift 20 -> conflict-free)
#define MM_STAGE ((MT + NT) * MM_ROWB)   // 30720
#define SM5_OFF  (3 * MM_STAGE)          // 92160
#define SMEM_TOT (SM5_OFF + 128 * 4 * 5 * 4)  // 102400

// ---- static device scratch ----
__device__ __align__(16) float g_d[NN * KK];
__device__ __align__(16) __nv_bfloat16 g_zc[(size_t)NN * KC2];   // 64 MB
__device__ __align__(16) __nv_bfloat16 g_mc[(size_t)KK * KC2];   // 2 MB
__device__ float g_a[NN];
__device__ float g_b[KK];
__device__ float g_t5p[NN * 4 * 5];                 // per-panel row top-5 partials
__device__ float g_rhoz[NN], g_sigz[NN];
__device__ float g_cspart[(size_t)(NN / 8) * KK];   // colsum(S) partials (16 MB)
__device__ float g_cs2[32 * KK];                    // second-level partials
__device__ float g_icolsum[KK];

// ---- helpers ----
__device__ __forceinline__ uint32_t s2u(const void* p) {
    uint32_t a;
    asm("{ .reg .u64 t; cvta.to.shared.u64 t, %1; cvt.u32.u64 %0, t; }"
        : "=r"(a) : "l"(p));
    return a;
}
__device__ __forceinline__ void cpa16(uint32_t dst, const void* src) {
    asm volatile("cp.async.cg.shared.global [%0], [%1], 16;" :: "r"(dst), "l"(src));
}
__device__ __forceinline__ void mma16816(float* c, const uint32_t* a, const uint32_t* b) {
    asm volatile("mma.sync.aligned.m16n8k16.row.col.f32.bf16.bf16.f32 "
        "{%0,%1,%2,%3}, {%4,%5,%6,%7}, {%8,%9}, {%0,%1,%2,%3};"
        : "+f"(c[0]), "+f"(c[1]), "+f"(c[2]), "+f"(c[3])
        : "r"(a[0]), "r"(a[1]), "r"(a[2]), "r"(a[3]), "r"(b[0]), "r"(b[1]));
}

// ---- sorted smallest-5 insertion ----
#define INS5(v, a0, a1, a2, a3, a4) do {                          \
    float _v = (v);                                               \
    if (_v < a4) {                                                \
        a4 = _v;                                                  \
        if (a4 < a3) { float _t = a3; a3 = a4; a4 = _t; }         \
        if (a3 < a2) { float _t = a2; a2 = a3; a3 = _t; }         \
        if (a2 < a1) { float _t = a1; a1 = a2; a2 = _t; }         \
        if (a1 < a0) { float _t = a0; a0 = a1; a1 = _t; }         \
    }                                                             \
} while (0)

// ======================= K0: fused row stats + bf16 [hi|lo] conversion ==============
__global__ void k_statscvt(const float* __restrict__ P, float* __restrict__ outstat,
                           __nv_bfloat16* __restrict__ C, float c2, float cadd) {
    int row  = blockIdx.x * 8 + (threadIdx.x >> 5);
    int lane = threadIdx.x & 31;
    const float* p = P + (size_t)row * DHH;
    __nv_bfloat16* cb = C + (size_t)row * KC2;
    float s = 0.f, ss = 0.f;
#pragma unroll
    for (int q = 0; q < 4; ++q) {
        int col = q * 128 + lane * 4;
        float4 v = *(const float4*)&p[col];
        s  += (v.x + v.y) + (v.z + v.w);
        ss += v.x * v.x + v.y * v.y + v.z * v.z + v.w * v.w;
        float f[4] = {v.x, v.y, v.z, v.w};
        unsigned short hu[4], lu[4];
#pragma unroll
        for (int i = 0; i < 4; ++i) {
            __nv_bfloat16 h = __float2bfloat16(f[i]);
            __nv_bfloat16 l = __float2bfloat16(f[i] - __bfloat162float(h));
            hu[i] = __bfloat16_as_ushort(h);
            lu[i] = __bfloat16_as_ushort(l);
        }
        uint2 hv = make_uint2(((uint32_t)hu[1] << 16) | hu[0],
                              ((uint32_t)hu[3] << 16) | hu[2]);
        uint2 lv = make_uint2(((uint32_t)lu[1] << 16) | lu[0],
                              ((uint32_t)lu[3] << 16) | lu[2]);
        *(uint2*)(cb + col)       = hv;
        *(uint2*)(cb + col + 512) = lv;
    }
#pragma unroll
    for (int off = 16; off > 0; off >>= 1) {
        s  += __shfl_xor_sync(0xffffffffu, s, off);
        ss += __shfl_xor_sync(0xffffffffu, ss, off);
    }
    if (lane == 0) outstat[row] = ss + c2 * s + cadd;
}

// ======================= K1: mma.sync GEMM + distance + row-top5 partials ===========
// logical K=1536 as 48 chunks; chunk c maps to physical panels:
//   Z : c<16 -> hi(c)      16<=c<32 -> lo(c-16)   c>=32 -> hi(c-32)
//   MU: c<16 -> hi(c)      16<=c<32 -> hi(c-16)   c>=32 -> lo(c-32)
__global__ void __launch_bounds__(256, 1) k_gemm() {
    extern __shared__ char smem_raw[];
    const int tid = threadIdx.x;
    const int wid = tid >> 5, lid = tid & 31;
    const int j0 = blockIdx.x * NT;
    const int i0 = blockIdx.y * MT;
    const int g = lid >> 2, t = lid & 3;
    const int wm = wid >> 2, wn = wid & 3;      // warp tile 64(M) x 64(N)
    char* sm = smem_raw;
    uint32_t smu = s2u(sm);
    float* sm5 = (float*)(smem_raw + SM5_OFF);   // [128 rows][4 wn][5]

    auto load_chunk = [&](int c) {
        uint32_t st = smu + (uint32_t)(c % 3) * MM_STAGE;
        int zo = (c < 16) ? c * 32 : (c < 32 ? 512 + (c - 16) * 32 : (c - 32) * 32);
        int mo = (c < 16) ? c * 32 : (c < 32 ? (c - 16) * 32 : 512 + (c - 32) * 32);
#pragma unroll
        for (int it = 0; it < 6; ++it) {            // 1536 x 16B per stage
            int idx = tid + it * 256;
            int row = idx >> 2, q = idx & 3;
            const __nv_bfloat16* src = (row < MT)
                ? g_zc + (size_t)(i0 + row) * KC2 + zo + q * 8
                : g_mc + (size_t)(j0 + row - MT) * KC2 + mo + q * 8;
            cpa16(st + (uint32_t)row * MM_ROWB + q * 16, src);
        }
    };

    float cacc[4][8][4];
#pragma unroll
    for (int mi = 0; mi < 4; ++mi)
#pragma unroll
        for (int ni = 0; ni < 8; ++ni)
#pragma unroll
            for (int q = 0; q < 4; ++q) cacc[mi][ni][q] = 0.f;

    load_chunk(0); asm volatile("cp.async.commit_group;" ::: "memory");
    load_chunk(1); asm volatile("cp.async.commit_group;" ::: "memory");
    load_chunk(2); asm volatile("cp.async.commit_group;" ::: "memory");

#pragma unroll 1
    for (int kt = 0; kt < MM_NCH; ++kt) {
        asm volatile("cp.async.wait_group 2;" ::: "memory");
        __syncthreads();
        const char* st = sm + (kt % 3) * MM_STAGE;
        const char* Ab = st + (wm * 64 + g) * MM_ROWB + t * 4;
        const char* Bb = st + MT * MM_ROWB + (wn * 64 + g) * MM_ROWB + t * 4;
#pragma unroll
        for (int ks = 0; ks < 2; ++ks) {
            uint32_t a[4][4], b[8][2];
#pragma unroll
            for (int mi = 0; mi < 4; ++mi) {
                const char* p = Ab + mi * 16 * MM_ROWB + ks * 32;
                a[mi][0] = *(const uint32_t*)(p);
                a[mi][1] = *(const uint32_t*)(p + 8 * MM_ROWB);
                a[mi][2] = *(const uint32_t*)(p + 16);
                a[mi][3] = *(const uint32_t*)(p + 8 * MM_ROWB + 16);
            }
#pragma unroll
            for (int ni = 0; ni < 8; ++ni) {
                const char* p = Bb + ni * 8 * MM_ROWB + ks * 32;
                b[ni][0] = *(const uint32_t*)(p);
                b[ni][1] = *(const uint32_t*)(p + 16);
            }
#pragma unroll
            for (int mi = 0; mi < 4; ++mi)
#pragma unroll
                for (int ni = 0; ni < 8; ++ni)
                    mma16816(cacc[mi][ni], a[mi], b[ni]);
        }
        __syncthreads();
        if (kt + 3 < MM_NCH) load_chunk(kt + 3);
        asm volatile("cp.async.commit_group;" ::: "memory");
    }

    // ---- epilogue: distance + per-warp row-top5 ----
#pragma unroll
    for (int mi = 0; mi < 4; ++mi) {
        int r0 = i0 + wm * 64 + mi * 16 + g;
        float a0 = g_a[r0], a1 = g_a[r0 + 8];
        float p0 = FBIG, p1 = FBIG, p2 = FBIG, p3 = FBIG, p4 = FBIG;  // row r0
        float q0 = FBIG, q1 = FBIG, q2 = FBIG, q3 = FBIG, q4 = FBIG;  // row r0+8
#pragma unroll
        for (int ni = 0; ni < 8; ++ni) {
            int cn = j0 + wn * 64 + ni * 8 + t * 2;
            float2 bb = *(const float2*)&g_b[cn];
            float2 o0, o1;
            o0.x = sqrtf(fmaxf(fmaf(-2.f, cacc[mi][ni][0], a0 + bb.x), 0.f));
            o0.y = sqrtf(fmaxf(fmaf(-2.f, cacc[mi][ni][1], a0 + bb.y), 0.f));
            o1.x = sqrtf(fmaxf(fmaf(-2.f, cacc[mi][ni][2], a1 + bb.x), 0.f));
            o1.y = sqrtf(fmaxf(fmaf(-2.f, cacc[mi][ni][3], a1 + bb.y), 0.f));
            *(float2*)&g_d[(size_t)r0 * KK + cn]       = o0;
            *(float2*)&g_d[(size_t)(r0 + 8) * KK + cn] = o1;
            INS5(o0.x, p0, p1, p2, p3, p4);
            INS5(o0.y, p0, p1, p2, p3, p4);
            INS5(o1.x, q0, q1, q2, q3, q4);
            INS5(o1.y, q0, q1, q2, q3, q4);
        }
        // merge across the 4 t-lanes of each quad (butterfly)
#pragma unroll
        for (int off = 1; off <= 2; off <<= 1) {
            float s0 = __shfl_xor_sync(0xffffffffu, p0, off);
            float s1 = __shfl_xor_sync(0xffffffffu, p1, off);
            float s2 = __shfl_xor_sync(0xffffffffu, p2, off);
            float s3 = __shfl_xor_sync(0xffffffffu, p3, off);
            float s4 = __shfl_xor_sync(0xffffffffu, p4, off);
            INS5(s0, p0, p1, p2, p3, p4);
            INS5(s1, p0, p1, p2, p3, p4);
            INS5(s2, p0, p1, p2, p3, p4);
            INS5(s3, p0, p1, p2, p3, p4);
            INS5(s4, p0, p1, p2, p3, p4);
            s0 = __shfl_xor_sync(0xffffffffu, q0, off);
            s1 = __shfl_xor_sync(0xffffffffu, q1, off);
            s2 = __shfl_xor_sync(0xffffffffu, q2, off);
            s3 = __shfl_xor_sync(0xffffffffu, q3, off);
            s4 = __shfl_xor_sync(0xffffffffu, q4, off);
            INS5(s0, q0, q1, q2, q3, q4);
            INS5(s1, q0, q1, q2, q3, q4);
            INS5(s2, q0, q1, q2, q3, q4);
            INS5(s3, q0, q1, q2, q3, q4);
            INS5(s4, q0, q1, q2, q3, q4);
        }
        if (t == 0) {
            int rl0 = wm * 64 + mi * 16 + g;
            float* d0 = sm5 + ((size_t)rl0 * 4 + wn) * 5;
            d0[0] = p0; d0[1] = p1; d0[2] = p2; d0[3] = p3; d0[4] = p4;
            float* d1 = sm5 + ((size_t)(rl0 + 8) * 4 + wn) * 5;
            d1[0] = q0; d1[1] = q1; d1[2] = q2; d1[3] = q3; d1[4] = q4;
        }
    }
    __syncthreads();
    // cross-wn merge: one thread per row
    if (tid < 128) {
        float t0 = FBIG, t1 = FBIG, t2 = FBIG, t3 = FBIG, t4 = FBIG;
        const float* p = sm5 + (size_t)tid * 20;
#pragma unroll
        for (int q = 0; q < 20; ++q) INS5(p[q], t0, t1, t2, t3, t4);
        float* o = g_t5p + ((size_t)(i0 + tid) * 4 + blockIdx.x) * 5;
        o[0] = t0; o[1] = t1; o[2] = t2; o[3] = t3; o[4] = t4;
    }
}

// ======================= K3: merge panel top5 + sigma bisection (fast) ===============
__global__ void k_solve() {
    int r = blockIdx.x * 256 + threadIdx.x;
    const float* pl = g_t5p + (size_t)r * 20;
    float t0 = FBIG, t1 = FBIG, t2 = FBIG, t3 = FBIG, t4 = FBIG;
#pragma unroll
    for (int q = 0; q < 20; ++q) INS5(pl[q], t0, t1, t2, t3, t4);
    float rho = t0;
    float e1 = t1 - rho, e2 = t2 - rho, e3 = t3 - rho, e4 = t4 - rho;
    float m0 = 0.f, m1 = 10000.f, sg = 1.f;
#pragma unroll 1
    for (int it = 0; it < NITER; ++it) {
        float inv = __fdividef(1.0f, sg);
        float cur = 1.0f
            + ((e1 > 0.f) ? __expf(-e1 * inv) : 1.0f)
            + ((e2 > 0.f) ? __expf(-e2 * inv) : 1.0f)
            + ((e3 > 0.f) ? __expf(-e3 * inv) : 1.0f)
            + ((e4 > 0.f) ? __expf(-e4 * inv) : 1.0f);
        if (cur > 1.5f) m1 = sg; else m0 = sg;
        sg = 0.5f * (m0 + m1);
    }
    g_rhoz[r] = rho;
    g_sigz[r] = sg;
}

// ======================= K4: W1 / S + rowsum + colsum partial =======================
__global__ void __launch_bounds__(256) k_w1s(float* __restrict__ W1a,
                                             float* __restrict__ S,
                                             float* __restrict__ W1b) {
    __shared__ float sc[8][KK];
    int wid  = threadIdx.x >> 5;
    int lane = threadIdx.x & 31;
    int row  = blockIdx.x * 8 + wid;
    float rho = g_rhoz[row];
    float invs = 1.0f / g_sigz[row];
    const float* dr = g_d + (size_t)row * KK;
    float w[32];
    float s = 0.f;
#pragma unroll
    for (int q = 0; q < 8; ++q) {
        float4 v = *(const float4*)&dr[q * 128 + lane * 4];
        float w0 = (v.x - rho > 0.f) ? expf(-(v.x - rho) * invs) : 1.0f;
        float w1 = (v.y - rho > 0.f) ? expf(-(v.y - rho) * invs) : 1.0f;
        float w2 = (v.z - rho > 0.f) ? expf(-(v.z - rho) * invs) : 1.0f;
        float w3 = (v.w - rho > 0.f) ? expf(-(v.w - rho) * invs) : 1.0f;
        w[q * 4 + 0] = w0; w[q * 4 + 1] = w1; w[q * 4 + 2] = w2; w[q * 4 + 3] = w3;
        s += (w0 + w1) + (w2 + w3);
    }
#pragma unroll
    for (int off = 16; off > 0; off >>= 1)
        s += __shfl_xor_sync(0xffffffffu, s, off);
    float rinv = 1.0f / s;
    size_t base = (size_t)row * KK;
#pragma unroll
    for (int q = 0; q < 8; ++q) {
        size_t o = base + q * 128 + lane * 4;
        float4 wv = make_float4(w[q * 4], w[q * 4 + 1], w[q * 4 + 2], w[q * 4 + 3]);
        float4 sv = make_float4(wv.x * rinv, wv.y * rinv, wv.z * rinv, wv.w * rinv);
        *(float4*)&W1a[o] = wv;
        *(float4*)&W1b[o] = wv;
        *(float4*)&S[o]   = sv;
        *(float4*)&sc[wid][q * 128 + lane * 4] = sv;
    }
    __syncthreads();
    int c4 = threadIdx.x * 4;
    float4 acc = make_float4(0.f, 0.f, 0.f, 0.f);
#pragma unroll
    for (int w2 = 0; w2 < 8; ++w2) {
        float4 v = *(const float4*)&sc[w2][c4];
        acc.x += v.x; acc.y += v.y; acc.z += v.z; acc.w += v.w;
    }
    *(float4*)&g_cspart[(size_t)blockIdx.x * KK + c4] = acc;
}

// ======================= K5: two-level colsum merge (coalesced) =======================
__global__ void k_csmerge1() {
    int col = blockIdx.x * 128 + threadIdx.x;
    const float* p = g_cspart + (size_t)blockIdx.y * 128 * KK + col;
    float acc = 0.f;
#pragma unroll 8
    for (int r = 0; r < 128; ++r) acc += p[(size_t)r * KK];
    g_cs2[blockIdx.y * KK + col] = acc;
}

__global__ void k_csmerge2() {
    int col = blockIdx.x * 128 + threadIdx.x;
    float acc = 0.f;
#pragma unroll
    for (int c = 0; c < 32; ++c) acc += g_cs2[c * KK + col];
    g_icolsum[col] = 1.0f / acc;
}

// ======================= K6: D =======================
__global__ void k_D(const float* __restrict__ S, float* __restrict__ D) {
    int row  = blockIdx.x * 8 + (threadIdx.x >> 5);
    int lane = threadIdx.x & 31;
    const float* sr = S + (size_t)row * KK;
    float t[32];
    float acc = 0.f;
#pragma unroll
    for (int q = 0; q < 8; ++q) {
        float4 v  = *(const float4*)&sr[q * 128 + lane * 4];
        float4 ic = *(const float4*)&g_icolsum[q * 128 + lane * 4];
        float t0 = v.x * v.x * ic.x;
        float t1 = v.y * v.y * ic.y;
        float t2 = v.z * v.z * ic.z;
        float t3 = v.w * v.w * ic.w;
        t[q * 4 + 0] = t0; t[q * 4 + 1] = t1; t[q * 4 + 2] = t2; t[q * 4 + 3] = t3;
        acc += (t0 + t1) + (t2 + t3);
    }
#pragma unroll
    for (int off = 16; off > 0; off >>= 1)
        acc += __shfl_xor_sync(0xffffffffu, acc, off);
    float rinv = 1.0f / acc;
    size_t base = (size_t)row * KK;
#pragma unroll
    for (int q = 0; q < 8; ++q) {
        size_t o = base + q * 128 + lane * 4;
        *(float4*)&D[o] = make_float4(t[q * 4] * rinv, t[q * 4 + 1] * rinv,
                                      t[q * 4 + 2] * rinv, t[q * 4 + 3] * rinv);
    }
}

// ======================= launch =======================
extern "C" void kernel_launch(void* const* d_in, const int* in_sizes, int n_in,
                              void* d_out, int out_size) {
    const float* Z  = (const float*)d_in[0];
    const float* MU = (const float*)d_in[1];
    float* out = (float*)d_out;
    float* W1a = out;
    float* S   = out + NKELT;
    float* W1b = out + 2 * NKELT;
    float* D   = out + 3 * NKELT;

    float *pa, *pb;
    __nv_bfloat16 *pzc, *pmc;
    cudaGetSymbolAddress((void**)&pa, g_a);
    cudaGetSymbolAddress((void**)&pb, g_b);
    cudaGetSymbolAddress((void**)&pzc, g_zc);
    cudaGetSymbolAddress((void**)&pmc, g_mc);

    cudaFuncSetAttribute(k_gemm, cudaFuncAttributeMaxDynamicSharedMemorySize,
                         SMEM_TOT);

    k_statscvt<<<NN / 8, 256>>>(Z, pa, pzc,   2.0f * EPSF, 512.0f * EPSF * EPSF);
    k_statscvt<<<KK / 8, 256>>>(MU, pb, pmc, -2.0f * EPSF, 0.0f);
    k_gemm<<<dim3(KK / NT, NN / MT), 256, SMEM_TOT>>>();
    k_solve<<<NN / 256, 256>>>();
    k_w1s<<<NN / 8, 256>>>(W1a, S, W1b);
    k_csmerge1<<<dim3(KK / 128, 32), 128>>>();
    k_csmerge2<<<KK / 128, 128>>>();
    k_D<<<NN / 8, 256>>>(S, D);
}